// round 7
// baseline (speedup 1.0000x reference)
#include <cuda_runtime.h>
#include <cuda_bf16.h>
#include <math.h>
#include <stdint.h>

// Problem constants
#define Bv    128
#define Nv    512
#define Dv    128
#define DEGv  8
#define MTOT  (Bv * Nv)            // 65536 nodes
#define Ev    (Bv * Nv * DEGv)     // 524288 edges
#define K1v   410
#define K2v   328

typedef unsigned long long ull;

// ---------------- scratch (static device globals; no allocations) ------------
__device__ float g_xn[MTOT * 128];   // X @ Wn (messages)
__device__ float g_xr[MTOT * 128];   // X @ Wr (root)
__device__ float g_h [MTOT * 128];   // conv1 output (later gated in place)
__device__ float g_h2[MTOT * 128];   // conv2 output (later gated in place)
__device__ float g_x1[Bv * 256];
__device__ float g_x2[Bv * 256];
__device__ unsigned char g_m1[MTOT];

// ---------------- packed f32x2 helpers ---------------------------------------
__device__ __forceinline__ ull pack2(float x) {
    ull r; unsigned u = __float_as_uint(x);
    asm("mov.b64 %0, {%1, %1};" : "=l"(r) : "r"(u));
    return r;
}
__device__ __forceinline__ ull fma2(ull a, ull b, ull c) {
    ull d;
    asm("fma.rn.f32x2 %0, %1, %2, %3;" : "=l"(d) : "l"(a), "l"(b), "l"(c));
    return d;
}
__device__ __forceinline__ void unpack2(ull v, float& lo, float& hi) {
    unsigned l, h;
    asm("mov.b64 {%0, %1}, %2;" : "=r"(l), "=r"(h) : "l"(v));
    lo = __uint_as_float(l); hi = __uint_as_float(h);
}

// ---------------- dual GEMM: outN = X@Wn, outR = X@Wr ------------------------
// X: [65536,128] row-major, Wn/Wr: [128,128] row-major (out = sum_k X[r][k]*W[k][c])
// Block: 64 rows x 256 cols (128 Wn-cols ++ 128 Wr-cols), 256 threads, 8x8 tile.
__global__ __launch_bounds__(256, 2)
void dual_gemm(const float* __restrict__ Xext,
               const float* __restrict__ Wn,
               const float* __restrict__ Wr,
               int useH) {
    const float* X = useH ? g_h : Xext;

    const int tid = threadIdx.x;
    const int tr  = tid & 7;          // 8 row groups
    const int tc  = tid >> 3;         // 32 col groups (warp = 4 tc x 8 tr)
    const int rowBase = blockIdx.x * 64;
    const int r0 = tr * 8;
    const int c0 = tc * 8;            // global col in [0,256)

    __shared__ __align__(16) float Ws[64][256];   // 64KB per k-chunk
    __shared__ float Xs[64][65];                  // [row][k], padded

    ull acc[8][4];
#pragma unroll
    for (int i = 0; i < 8; i++)
#pragma unroll
        for (int j = 0; j < 4; j++) acc[i][j] = 0ULL;

    for (int k0 = 0; k0 < 128; k0 += 64) {
        // load W chunk (both matrices side by side)
        for (int i = tid; i < 64 * 128; i += 256) {
            int kk = i >> 7, c = i & 127;
            Ws[kk][c]       = Wn[(k0 + kk) * 128 + c];
            Ws[kk][128 + c] = Wr[(k0 + kk) * 128 + c];
        }
        // load X chunk
        for (int i = tid; i < 64 * 64; i += 256) {
            int r = i >> 6, kk = i & 63;
            Xs[r][kk] = X[(size_t)(rowBase + r) * 128 + k0 + kk];
        }
        __syncthreads();

#pragma unroll 4
        for (int kk = 0; kk < 64; kk++) {
            const ull* wrow = (const ull*)&Ws[kk][c0];
            ull b0 = wrow[0], b1 = wrow[1], b2 = wrow[2], b3 = wrow[3];
#pragma unroll
            for (int i = 0; i < 8; i++) {
                ull a = pack2(Xs[r0 + i][kk]);
                acc[i][0] = fma2(a, b0, acc[i][0]);
                acc[i][1] = fma2(a, b1, acc[i][1]);
                acc[i][2] = fma2(a, b2, acc[i][2]);
                acc[i][3] = fma2(a, b3, acc[i][3]);
            }
        }
        __syncthreads();
    }

    // epilogue
#pragma unroll
    for (int i = 0; i < 8; i++) {
        size_t row = (size_t)(rowBase + r0 + i);
        float v[8];
#pragma unroll
        for (int j = 0; j < 4; j++) unpack2(acc[i][j], v[2 * j], v[2 * j + 1]);
        float4 f0 = make_float4(v[0], v[1], v[2], v[3]);
        float4 f1 = make_float4(v[4], v[5], v[6], v[7]);
        if (c0 < 128) {
            float* o = g_xn + row * 128 + c0;
            *(float4*)(o)     = f0;
            *(float4*)(o + 4) = f1;
        } else {
            float* o = g_xr + row * 128 + (c0 - 128);
            *(float4*)(o)     = f0;
            *(float4*)(o + 4) = f1;
        }
    }
}

// ---------------- edge aggregation + conv epilogue ---------------------------
// grid: (8 feature chunks of 16, 128 graphs), 512 threads
// H = relu(xr + segment_sum(xn[src] -> dst) + bias)
__global__ __launch_bounds__(512)
void agg_finish(const int* __restrict__ eidx, const float* __restrict__ bias, int pass) {
    float* H = pass ? g_h2 : g_h;
    const int b  = blockIdx.y;
    const int fb = blockIdx.x * 16;
    const int tid = threadIdx.x;

    __shared__ float sagg[512 * 16];   // 32KB
    for (int i = tid; i < 512 * 16; i += 512) sagg[i] = 0.f;
    __syncthreads();

    const int* srcA = eidx;
    const int* dstA = eidx + Ev;
    const int lane = tid & 31, w = tid >> 5;
    const int half = lane >> 4;
    const int f    = lane & 15;
    const int ebase = b * (Nv * DEGv);
    const int nbase = b * Nv;

    for (int it = 0; it < 128; it++) {
        int e = ebase + (it * 16 + w) * 2 + half;
        int s = srcA[e];
        int d = dstA[e];
        float v = g_xn[(size_t)s * 128 + fb + f];
        atomicAdd(&sagg[(d - nbase) * 16 + f], v);
    }
    __syncthreads();

    for (int i = tid; i < 512 * 16; i += 512) {
        int node = i >> 4, fl = i & 15;
        size_t gi = (size_t)(nbase + node) * 128 + fb + fl;
        float v = g_xr[gi] + sagg[i] + bias[fb + fl];
        H[gi] = fmaxf(v, 0.f);
    }
}

// ---------------- per-graph pooling: score, exact top-K, gate, readout -------
// 128 blocks x 512 threads. Gates H in place, writes readout [max(128)|mean(128)].
__global__ __launch_bounds__(512)
void pool_kernel(const float* __restrict__ p, int pass) {
    const int b = blockIdx.x;
    float* H   = pass ? g_h2 : g_h;
    float* out = pass ? g_x2 : g_x1;
    const int K = pass ? K2v : K1v;

    __shared__ float sp[128];
    __shared__ float ssc[512];
    __shared__ float sgate[512];
    __shared__ unsigned char skept[512];
    __shared__ float sred[8 * 128];
    __shared__ float s_invn;

    const int tid = threadIdx.x;
    const size_t base = (size_t)b * Nv;

    if (tid < 128) sp[tid] = p[tid];
    __syncthreads();
    if (tid < 32) {
        float v = sp[tid] * sp[tid] + sp[tid + 32] * sp[tid + 32]
                + sp[tid + 64] * sp[tid + 64] + sp[tid + 96] * sp[tid + 96];
        for (int o = 16; o > 0; o >>= 1) v += __shfl_xor_sync(0xffffffffu, v, o);
        if (tid == 0) s_invn = 1.0f / sqrtf(v);
    }
    __syncthreads();

    // scores: warp computes 32 node dots
    const int w = tid >> 5, lane = tid & 31;
    for (int it = 0; it < 32; it++) {
        int node = w * 32 + it;
        const float* hr = H + (base + node) * 128;
        float v = hr[lane] * sp[lane] + hr[lane + 32] * sp[lane + 32]
                + hr[lane + 64] * sp[lane + 64] + hr[lane + 96] * sp[lane + 96];
        for (int o = 16; o > 0; o >>= 1) v += __shfl_xor_sync(0xffffffffu, v, o);
        if (lane == 0) {
            float sc = v * s_invn;
            if (pass && !g_m1[base + node]) sc = -INFINITY;
            ssc[node] = sc;
        }
    }
    __syncthreads();

    // exact stable-top-K via rank (matches lax.top_k tie-break by lower index)
    {
        float my = ssc[tid];
        int cnt = 0;
        for (int j = 0; j < 512; j++) {
            float sj = ssc[j];
            cnt += (sj > my) || (sj == my && j < tid);
        }
        bool kept = cnt < K;
        skept[tid] = kept ? 1 : 0;
        sgate[tid] = kept ? tanhf(my) : 0.f;
        if (!pass) g_m1[base + tid] = kept ? 1 : 0;
    }
    __syncthreads();

    // gate in place + fused max/mean readout
    {
        const int f = tid & 127, grp = tid >> 7;
        float fsum = 0.f, fmaxv = -INFINITY;
        for (int n = grp; n < 512; n += 4) {
            size_t gi = (base + n) * 128 + f;
            float v = H[gi] * sgate[n];
            H[gi] = v;
            fsum += v;
            if (skept[n]) fmaxv = fmaxf(fmaxv, v);
        }
        sred[grp * 128 + f]       = fsum;
        sred[512 + grp * 128 + f] = fmaxv;
    }
    __syncthreads();
    if (tid < 128) {
        float s = sred[tid] + sred[128 + tid] + sred[256 + tid] + sred[384 + tid];
        float m = fmaxf(fmaxf(sred[512 + tid], sred[640 + tid]),
                        fmaxf(sred[768 + tid], sred[896 + tid]));
        out[b * 256 + tid]       = m;           // global max pool
        out[b * 256 + 128 + tid] = s / (float)K; // global mean pool
    }
}

// ---------------- MLP head ---------------------------------------------------
__global__ __launch_bounds__(128)
void mlp_kernel(const float* __restrict__ lw1, const float* __restrict__ lb1,
                const float* __restrict__ lw2, const float* __restrict__ lb2,
                const float* __restrict__ lw3, const float* __restrict__ lb3,
                float* __restrict__ outp) {
    const int b = blockIdx.x;
    const int tid = threadIdx.x;  // 128
    __shared__ float sz[256], s1m[128], s2m[64];

    sz[tid]       = g_x1[b * 256 + tid]       + g_x2[b * 256 + tid];
    sz[tid + 128] = g_x1[b * 256 + 128 + tid] + g_x2[b * 256 + 128 + tid];
    __syncthreads();

    float a = lb1[tid];
#pragma unroll 8
    for (int i = 0; i < 256; i++) a += sz[i] * lw1[i * 128 + tid];
    s1m[tid] = fmaxf(a, 0.f);
    __syncthreads();

    if (tid < 64) {
        float a2 = lb2[tid];
#pragma unroll 8
        for (int i = 0; i < 128; i++) a2 += s1m[i] * lw2[i * 64 + tid];
        s2m[tid] = fmaxf(a2, 0.f);
    }
    __syncthreads();

    if (tid < 32) {
        float v = s2m[tid] * lw3[tid] + s2m[tid + 32] * lw3[tid + 32];
        for (int o = 16; o > 0; o >>= 1) v += __shfl_xor_sync(0xffffffffu, v, o);
        if (tid == 0) outp[b] = 1.0f / (1.0f + expf(-(v + lb3[0])));
    }
}

// ---------------- launch -----------------------------------------------------
extern "C" void kernel_launch(void* const* d_in, const int* in_sizes, int n_in,
                              void* d_out, int out_size) {
    const float* x   = (const float*)d_in[0];
    const int*   ei  = (const int*)  d_in[1];
    const float* W1r = (const float*)d_in[2];
    const float* W1n = (const float*)d_in[3];
    const float* b1  = (const float*)d_in[4];
    const float* p1  = (const float*)d_in[5];
    const float* W2r = (const float*)d_in[6];
    const float* W2n = (const float*)d_in[7];
    const float* b2  = (const float*)d_in[8];
    const float* p2  = (const float*)d_in[9];
    const float* lw1 = (const float*)d_in[10];
    const float* lb1 = (const float*)d_in[11];
    const float* lw2 = (const float*)d_in[12];
    const float* lb2 = (const float*)d_in[13];
    const float* lw3 = (const float*)d_in[14];
    const float* lb3 = (const float*)d_in[15];
    float* out = (float*)d_out;

    // conv1
    dual_gemm<<<MTOT / 64, 256>>>(x, W1n, W1r, 0);
    agg_finish<<<dim3(8, Bv), 512>>>(ei, b1, 0);
    pool_kernel<<<Bv, 512>>>(p1, 0);
    // conv2 (reads gated g_h)
    dual_gemm<<<MTOT / 64, 256>>>(nullptr, W2n, W2r, 1);
    agg_finish<<<dim3(8, Bv), 512>>>(ei, b2, 1);
    pool_kernel<<<Bv, 512>>>(p2, 1);
    // head
    mlp_kernel<<<Bv, 128>>>(lw1, lb1, lw2, lb2, lw3, lb3, out);
}

// round 9
// speedup vs baseline: 1.6746x; 1.6746x over previous
#include <cuda_runtime.h>
#include <cuda_bf16.h>
#include <math.h>
#include <stdint.h>

// Problem constants
#define Bv    128
#define Nv    512
#define Dv    128
#define DEGv  8
#define MTOT  (Bv * Nv)            // 65536 nodes
#define Ev    (Bv * Nv * DEGv)     // 524288 edges
#define K1v   410
#define K2v   328

typedef unsigned long long ull;

// ---------------- scratch (static device globals; no allocations) ------------
__device__ float g_h [MTOT * 128];   // conv1 output (gated in place by pool1)
__device__ float g_h2[MTOT * 128];   // conv2 output (gated in place by pool2)
__device__ float g_ax[MTOT * 128];   // aggregated neighbor features
__device__ float g_x1[Bv * 256];
__device__ float g_x2[Bv * 256];
__device__ unsigned char g_m1[MTOT];
// CSR scratch
__device__ int g_deg[MTOT];
__device__ int g_off[MTOT];
__device__ int g_cur[MTOT];
__device__ int g_srcl[Ev];

// ---------------- packed f32x2 helpers ---------------------------------------
__device__ __forceinline__ ull pack2(float x) {
    ull r; unsigned u = __float_as_uint(x);
    asm("mov.b64 %0, {%1, %1};" : "=l"(r) : "r"(u));
    return r;
}
__device__ __forceinline__ ull fma2(ull a, ull b, ull c) {
    ull d;
    asm("fma.rn.f32x2 %0, %1, %2, %3;" : "=l"(d) : "l"(a), "l"(b), "l"(c));
    return d;
}
__device__ __forceinline__ void unpack2(ull v, float& lo, float& hi) {
    unsigned l, h;
    asm("mov.b64 {%0, %1}, %2;" : "=r"(l), "=r"(h) : "l"(v));
    lo = __uint_as_float(l); hi = __uint_as_float(h);
}

// ---------------- CSR build ---------------------------------------------------
__global__ void zero_kernel() {
    int i = blockIdx.x * blockDim.x + threadIdx.x;
    if (i < MTOT) { g_deg[i] = 0; g_cur[i] = 0; }
}

__global__ void count_kernel(const int* __restrict__ ei) {
    int e = blockIdx.x * blockDim.x + threadIdx.x;
    if (e < Ev) atomicAdd(&g_deg[ei[Ev + e]], 1);
}

// per-graph exclusive scan: each graph has exactly N*DEG = 4096 edges
__global__ __launch_bounds__(512)
void scan_kernel() {
    __shared__ int s[512];
    const int b = blockIdx.x, tid = threadIdx.x;
    const int node = b * 512 + tid;
    int d = g_deg[node];
    s[tid] = d;
    __syncthreads();
    for (int o = 1; o < 512; o <<= 1) {
        int v = (tid >= o) ? s[tid - o] : 0;
        __syncthreads();
        s[tid] += v;
        __syncthreads();
    }
    g_off[node] = b * 4096 + s[tid] - d;   // exclusive prefix, graph-local base
}

__global__ void scatter_kernel(const int* __restrict__ ei) {
    int e = blockIdx.x * blockDim.x + threadIdx.x;
    if (e < Ev) {
        int d = ei[Ev + e];
        int p = atomicAdd(&g_cur[d], 1);
        g_srcl[g_off[d] + p] = ei[e];
    }
}

// ---------------- neighbor aggregation: warp per node -------------------------
__global__ __launch_bounds__(256)
void aggregate_kernel(const float* __restrict__ Xext, int useH) {
    const float* X = useH ? g_h : Xext;
    const int gw = (blockIdx.x * 256 + threadIdx.x) >> 5;   // node id
    const int lane = threadIdx.x & 31;
    const int off = g_off[gw];
    const int deg = g_deg[gw];
    float4 acc = make_float4(0.f, 0.f, 0.f, 0.f);
    for (int j = 0; j < deg; j++) {
        int s = g_srcl[off + j];
        float4 v = *(const float4*)&X[(size_t)s * 128 + (lane << 2)];
        acc.x += v.x; acc.y += v.y; acc.z += v.z; acc.w += v.w;
    }
    *(float4*)&g_ax[(size_t)gw * 128 + (lane << 2)] = acc;
}

// ---------------- fused conv GEMM: H = relu([X|AX] @ [Wr;Wn] + b) --------------
// 512 blocks x 256 threads; tile 128 rows x 128 cols, 8x8 per thread.
// Row mapping r = tr + 16*i -> X LDS hits 16 consecutive banks (conflict-free).
__global__ __launch_bounds__(256, 2)
void fused_gemm(const float* __restrict__ Xext,
                const float* __restrict__ Wr,
                const float* __restrict__ Wn,
                const float* __restrict__ bias,
                int pass) {
    const float* A1 = pass ? g_h : Xext;
    const float* A2 = g_ax;
    float* Hout = pass ? g_h2 : g_h;

    const int tid = threadIdx.x;
    const int tr = tid & 15;          // 16 row groups (rows tr, tr+16, ..., tr+112)
    const int tc = tid >> 4;          // 16 col groups
    const int c0 = tc * 8;
    const int rowBase = blockIdx.x * 128;

    __shared__ __align__(16) float Ws[64][128];   // 32 KB
    __shared__ float Xs[128][65];                 // 33.3 KB, conflict-free reads

    ull acc[8][4];
#pragma unroll
    for (int i = 0; i < 8; i++)
#pragma unroll
        for (int j = 0; j < 4; j++) acc[i][j] = 0ULL;

#pragma unroll 1
    for (int c = 0; c < 4; c++) {
        const float* A = (c < 2) ? A1 : A2;
        const float* W = (c < 2) ? Wr : Wn;
        const int k0 = (c & 1) * 64;

        // load W chunk [64 k x 128 c], float4, coalesced
#pragma unroll
        for (int t = 0; t < 8; t++) {
            int i = tid + t * 256;
            int rw = i >> 5, c4 = (i & 31) << 2;
            *(float4*)&Ws[rw][c4] = *(const float4*)&W[(k0 + rw) * 128 + c4];
        }
        // load X chunk [128 rows x 64 k], scalar, coalesced (fixed kk per thread)
        {
            int kk = tid & 63;
            int rb = tid >> 6;
#pragma unroll
            for (int t = 0; t < 32; t++) {
                int r = rb + 4 * t;
                Xs[r][kk] = A[(size_t)(rowBase + r) * 128 + k0 + kk];
            }
        }
        __syncthreads();

#pragma unroll 4
        for (int kk = 0; kk < 64; kk++) {
            float4 w0 = *(const float4*)&Ws[kk][c0];
            float4 w1 = *(const float4*)&Ws[kk][c0 + 4];
            ull b0 = *(ull*)&w0.x, b1 = *(ull*)&w0.z;
            ull b2 = *(ull*)&w1.x, b3 = *(ull*)&w1.z;
#pragma unroll
            for (int i = 0; i < 8; i++) {
                ull a = pack2(Xs[tr + 16 * i][kk]);
                acc[i][0] = fma2(a, b0, acc[i][0]);
                acc[i][1] = fma2(a, b1, acc[i][1]);
                acc[i][2] = fma2(a, b2, acc[i][2]);
                acc[i][3] = fma2(a, b3, acc[i][3]);
            }
        }
        __syncthreads();
    }

    // epilogue: + bias, relu, store
    float bb[8];
    {
        float4 f0 = *(const float4*)&bias[c0];
        float4 f1 = *(const float4*)&bias[c0 + 4];
        bb[0] = f0.x; bb[1] = f0.y; bb[2] = f0.z; bb[3] = f0.w;
        bb[4] = f1.x; bb[5] = f1.y; bb[6] = f1.z; bb[7] = f1.w;
    }
#pragma unroll
    for (int i = 0; i < 8; i++) {
        size_t row = (size_t)(rowBase + tr + 16 * i);
        float v[8];
#pragma unroll
        for (int j = 0; j < 4; j++) unpack2(acc[i][j], v[2 * j], v[2 * j + 1]);
#pragma unroll
        for (int j = 0; j < 8; j++) v[j] = fmaxf(v[j] + bb[j], 0.f);
        float* o = Hout + row * 128 + c0;
        *(float4*)(o)     = make_float4(v[0], v[1], v[2], v[3]);
        *(float4*)(o + 4) = make_float4(v[4], v[5], v[6], v[7]);
    }
}

// ---------------- per-graph pooling: score, exact top-K, gate, readout -------
__global__ __launch_bounds__(512)
void pool_kernel(const float* __restrict__ p, int pass) {
    const int b = blockIdx.x;
    float* H   = pass ? g_h2 : g_h;
    float* out = pass ? g_x2 : g_x1;
    const int K = pass ? K2v : K1v;

    __shared__ float sp[128];
    __shared__ float ssc[512];
    __shared__ float sgate[512];
    __shared__ unsigned char skept[512];
    __shared__ float sred[8 * 128];
    __shared__ float s_invn;

    const int tid = threadIdx.x;
    const size_t base = (size_t)b * Nv;

    if (tid < 128) sp[tid] = p[tid];
    __syncthreads();
    if (tid < 32) {
        float v = sp[tid] * sp[tid] + sp[tid + 32] * sp[tid + 32]
                + sp[tid + 64] * sp[tid + 64] + sp[tid + 96] * sp[tid + 96];
        for (int o = 16; o > 0; o >>= 1) v += __shfl_xor_sync(0xffffffffu, v, o);
        if (tid == 0) s_invn = 1.0f / sqrtf(v);
    }
    __syncthreads();

    const int w = tid >> 5, lane = tid & 31;
    for (int it = 0; it < 32; it++) {
        int node = w * 32 + it;
        const float* hr = H + (base + node) * 128;
        float v = hr[lane] * sp[lane] + hr[lane + 32] * sp[lane + 32]
                + hr[lane + 64] * sp[lane + 64] + hr[lane + 96] * sp[lane + 96];
        for (int o = 16; o > 0; o >>= 1) v += __shfl_xor_sync(0xffffffffu, v, o);
        if (lane == 0) {
            float sc = v * s_invn;
            if (pass && !g_m1[base + node]) sc = -INFINITY;
            ssc[node] = sc;
        }
    }
    __syncthreads();

    // exact stable-top-K via rank (matches lax.top_k tie-break by lower index)
    {
        float my = ssc[tid];
        int cnt = 0;
        for (int j = 0; j < 512; j++) {
            float sj = ssc[j];
            cnt += (sj > my) || (sj == my && j < tid);
        }
        bool kept = cnt < K;
        skept[tid] = kept ? 1 : 0;
        sgate[tid] = kept ? tanhf(my) : 0.f;
        if (!pass) g_m1[base + tid] = kept ? 1 : 0;
    }
    __syncthreads();

    // gate in place + fused max/mean readout
    {
        const int f = tid & 127, grp = tid >> 7;
        float fsum = 0.f, fmaxv = -INFINITY;
        for (int n = grp; n < 512; n += 4) {
            size_t gi = (base + n) * 128 + f;
            float v = H[gi] * sgate[n];
            H[gi] = v;
            fsum += v;
            if (skept[n]) fmaxv = fmaxf(fmaxv, v);
        }
        sred[grp * 128 + f]       = fsum;
        sred[512 + grp * 128 + f] = fmaxv;
    }
    __syncthreads();
    if (tid < 128) {
        float s = sred[tid] + sred[128 + tid] + sred[256 + tid] + sred[384 + tid];
        float m = fmaxf(fmaxf(sred[512 + tid], sred[640 + tid]),
                        fmaxf(sred[768 + tid], sred[896 + tid]));
        out[b * 256 + tid]       = m;
        out[b * 256 + 128 + tid] = s / (float)K;
    }
}

// ---------------- MLP head ---------------------------------------------------
__global__ __launch_bounds__(128)
void mlp_kernel(const float* __restrict__ lw1, const float* __restrict__ lb1,
                const float* __restrict__ lw2, const float* __restrict__ lb2,
                const float* __restrict__ lw3, const float* __restrict__ lb3,
                float* __restrict__ outp) {
    const int b = blockIdx.x;
    const int tid = threadIdx.x;  // 128
    __shared__ float sz[256], s1m[128], s2m[64];

    sz[tid]       = g_x1[b * 256 + tid]       + g_x2[b * 256 + tid];
    sz[tid + 128] = g_x1[b * 256 + 128 + tid] + g_x2[b * 256 + 128 + tid];
    __syncthreads();

    float a = lb1[tid];
#pragma unroll 8
    for (int i = 0; i < 256; i++) a += sz[i] * lw1[i * 128 + tid];
    s1m[tid] = fmaxf(a, 0.f);
    __syncthreads();

    if (tid < 64) {
        float a2 = lb2[tid];
#pragma unroll 8
        for (int i = 0; i < 128; i++) a2 += s1m[i] * lw2[i * 64 + tid];
        s2m[tid] = fmaxf(a2, 0.f);
    }
    __syncthreads();

    if (tid < 32) {
        float v = s2m[tid] * lw3[tid] + s2m[tid + 32] * lw3[tid + 32];
        for (int o = 16; o > 0; o >>= 1) v += __shfl_xor_sync(0xffffffffu, v, o);
        if (tid == 0) outp[b] = 1.0f / (1.0f + expf(-(v + lb3[0])));
    }
}

// ---------------- launch -----------------------------------------------------
extern "C" void kernel_launch(void* const* d_in, const int* in_sizes, int n_in,
                              void* d_out, int out_size) {
    const float* x   = (const float*)d_in[0];
    const int*   ei  = (const int*)  d_in[1];
    const float* W1r = (const float*)d_in[2];
    const float* W1n = (const float*)d_in[3];
    const float* b1  = (const float*)d_in[4];
    const float* p1  = (const float*)d_in[5];
    const float* W2r = (const float*)d_in[6];
    const float* W2n = (const float*)d_in[7];
    const float* b2  = (const float*)d_in[8];
    const float* p2  = (const float*)d_in[9];
    const float* lw1 = (const float*)d_in[10];
    const float* lb1 = (const float*)d_in[11];
    const float* lw2 = (const float*)d_in[12];
    const float* lb2 = (const float*)d_in[13];
    const float* lw3 = (const float*)d_in[14];
    const float* lb3 = (const float*)d_in[15];
    float* out = (float*)d_out;

    // CSR build (reused by both convs)
    zero_kernel<<<256, 256>>>();
    count_kernel<<<Ev / 256, 256>>>(ei);
    scan_kernel<<<Bv, 512>>>();
    scatter_kernel<<<Ev / 256, 256>>>(ei);

    // conv1: aggregate raw x, then fused GEMM K=256 (+bias+relu)
    aggregate_kernel<<<MTOT / 8, 256>>>(x, 0);
    fused_gemm<<<MTOT / 128, 256>>>(x, W1r, W1n, b1, 0);
    pool_kernel<<<Bv, 512>>>(p1, 0);

    // conv2: aggregate gated h, fused GEMM
    aggregate_kernel<<<MTOT / 8, 256>>>(nullptr, 1);
    fused_gemm<<<MTOT / 128, 256>>>(nullptr, W2r, W2n, b2, 1);
    pool_kernel<<<Bv, 512>>>(p2, 1);

    // head
    mlp_kernel<<<Bv, 128>>>(lw1, lb1, lw2, lb2, lw3, lb3, out);
}

// round 13
// speedup vs baseline: 2.1548x; 1.2867x over previous
#include <cuda_runtime.h>
#include <cuda_bf16.h>
#include <math.h>
#include <stdint.h>

// Problem constants
#define Bv    128
#define Nv    512
#define DEGv  8
#define MTOT  (Bv * Nv)            // 65536 nodes
#define Ev    (Bv * Nv * DEGv)     // 524288 edges
#define K1v   410
#define K2v   328

// ---------------- scratch (static device globals; no allocations) ------------
__device__ float g_h [MTOT * 128];   // conv1 output (gated in place by pool1)
__device__ float g_h2[MTOT * 128];   // conv2 output (gated in place by pool2)
__device__ float g_x1[Bv * 256];
__device__ float g_x2[Bv * 256];
__device__ unsigned char g_m1[MTOT];
// bf16 split operands for tensor GEMM: A = [X | AX], 65536 x 256
__device__ __nv_bfloat16 g_ahi[MTOT * 256];
__device__ __nv_bfloat16 g_alo[MTOT * 256];
// W transposed+split: [128 n][256 k] (k<128 -> Wr, k>=128 -> Wn)
__device__ __nv_bfloat16 g_wth[128 * 256];
__device__ __nv_bfloat16 g_wtl[128 * 256];
// CSR scratch
__device__ int g_deg[MTOT];
__device__ int g_off[MTOT];
__device__ int g_cur[MTOT];
__device__ int g_srcl[Ev];

// ---------------- small helpers ----------------------------------------------
__device__ __forceinline__ uint32_t smem_u32(const void* p) {
    uint32_t a;
    asm("{ .reg .u64 t; cvta.to.shared.u64 t, %1; cvt.u32.u64 %0, t; }" : "=r"(a) : "l"(p));
    return a;
}
__device__ __forceinline__ uint32_t pack_bf2(float a, float b) {
    __nv_bfloat162 t = __floats2bfloat162_rn(a, b);
    return *(uint32_t*)&t;
}
__device__ __forceinline__ void bf_split(float v, float& hi, float& lo) {
    __nv_bfloat16 h = __float2bfloat16(v);
    hi = __bfloat162float(h);
    lo = v - hi;
}
__device__ __forceinline__ void ldsm_x4(uint32_t* r, uint32_t addr) {
    asm volatile("ldmatrix.sync.aligned.m8n8.x4.shared.b16 {%0,%1,%2,%3}, [%4];"
        : "=r"(r[0]), "=r"(r[1]), "=r"(r[2]), "=r"(r[3]) : "r"(addr));
}
__device__ __forceinline__ void mma_bf16(float* c, const uint32_t* a, uint32_t b0, uint32_t b1) {
    asm volatile(
        "mma.sync.aligned.m16n8k16.row.col.f32.bf16.bf16.f32 "
        "{%0,%1,%2,%3}, {%4,%5,%6,%7}, {%8,%9}, {%0,%1,%2,%3};"
        : "+f"(c[0]), "+f"(c[1]), "+f"(c[2]), "+f"(c[3])
        : "r"(a[0]), "r"(a[1]), "r"(a[2]), "r"(a[3]), "r"(b0), "r"(b1));
}

// ---------------- CSR build ---------------------------------------------------
__global__ void zero_kernel() {
    int i = blockIdx.x * blockDim.x + threadIdx.x;
    if (i < MTOT) { g_deg[i] = 0; g_cur[i] = 0; }
}
__global__ void count_kernel(const int* __restrict__ ei) {
    int e = blockIdx.x * blockDim.x + threadIdx.x;
    if (e < Ev) atomicAdd(&g_deg[ei[Ev + e]], 1);
}
__global__ __launch_bounds__(512)
void scan_kernel() {
    __shared__ int s[512];
    const int b = blockIdx.x, tid = threadIdx.x;
    const int node = b * 512 + tid;
    int d = g_deg[node];
    s[tid] = d;
    __syncthreads();
    for (int o = 1; o < 512; o <<= 1) {
        int v = (tid >= o) ? s[tid - o] : 0;
        __syncthreads();
        s[tid] += v;
        __syncthreads();
    }
    g_off[node] = b * 4096 + s[tid] - d;
}
__global__ void scatter_kernel(const int* __restrict__ ei) {
    int e = blockIdx.x * blockDim.x + threadIdx.x;
    if (e < Ev) {
        int d = ei[Ev + e];
        int p = atomicAdd(&g_cur[d], 1);
        g_srcl[g_off[d] + p] = ei[e];
    }
}

// ---------------- weight prep: transpose + bf16 hi/lo split -------------------
__global__ __launch_bounds__(256)
void prep_w(const float* __restrict__ Wr, const float* __restrict__ Wn) {
    int e = blockIdx.x * blockDim.x + threadIdx.x;   // 32768
    int n = e >> 8, k = e & 255;
    float v = (k < 128) ? Wr[k * 128 + n] : Wn[(k - 128) * 128 + n];
    float hi, lo;
    bf_split(v, hi, lo);
    g_wth[e] = __float2bfloat16(hi);
    g_wtl[e] = __float2bfloat16_rn(lo);
}

// ---------------- X-half conversion: cols 0..127 of A -------------------------
__global__ __launch_bounds__(256)
void convert_x(const float* __restrict__ Xext, int pass) {
    const float* X = pass ? g_h : Xext;
    int idx = blockIdx.x * blockDim.x + threadIdx.x;
    int row = idx >> 5, q = idx & 31;
    float4 v = *(const float4*)&X[(size_t)row * 128 + q * 4];
    float h0, l0, h1, l1, h2, l2, h3, l3;
    bf_split(v.x, h0, l0); bf_split(v.y, h1, l1);
    bf_split(v.z, h2, l2); bf_split(v.w, h3, l3);
    size_t o = (size_t)row * 256 + q * 4;
    *(uint2*)&g_ahi[o] = make_uint2(pack_bf2(h0, h1), pack_bf2(h2, h3));
    *(uint2*)&g_alo[o] = make_uint2(pack_bf2(l0, l1), pack_bf2(l2, l3));
}

// ---------------- neighbor aggregation -> bf16 hi/lo (cols 128..255) ----------
__global__ __launch_bounds__(256)
void aggregate_kernel(const float* __restrict__ Xext, int useH) {
    const float* X = useH ? g_h : Xext;
    const int gw = (blockIdx.x * 256 + threadIdx.x) >> 5;
    const int lane = threadIdx.x & 31;
    const int off = g_off[gw];
    const int deg = g_deg[gw];
    float4 acc = make_float4(0.f, 0.f, 0.f, 0.f);
    for (int j = 0; j < deg; j++) {
        int s = g_srcl[off + j];
        float4 v = *(const float4*)&X[(size_t)s * 128 + (lane << 2)];
        acc.x += v.x; acc.y += v.y; acc.z += v.z; acc.w += v.w;
    }
    float h0, l0, h1, l1, h2, l2, h3, l3;
    bf_split(acc.x, h0, l0); bf_split(acc.y, h1, l1);
    bf_split(acc.z, h2, l2); bf_split(acc.w, h3, l3);
    size_t o = (size_t)gw * 256 + 128 + (lane << 2);
    *(uint2*)&g_ahi[o] = make_uint2(pack_bf2(h0, h1), pack_bf2(h2, h3));
    *(uint2*)&g_alo[o] = make_uint2(pack_bf2(l0, l1), pack_bf2(l2, l3));
}

// ---------------- tensor-core conv GEMM via mma.sync (HMMA fallback) ----------
// H = relu(A @ Wt^T + b); A=[65536,256] bf16 hi/lo, Wt=[128,256] bf16 hi/lo.
// Per CTA: 128 rows x 128 cols, K=256 in 4 chunks of 64.
// 3-product compensation: Ahi*Whi + Ahi*Wlo + Alo*Whi, fp32 accumulators.
// smem: 4 tiles of [128][64] bf16 (16KB each, SW<3,4,3>) + 128 bias floats.
#define TILE_B   16384
#define SM_BIAS  (4 * TILE_B)
#define SM_TOTAL (SM_BIAS + 512)

__device__ __forceinline__ uint32_t sw_addr(uint32_t sbase, int tile, int row, int kb) {
    uint32_t off = (uint32_t)(row * 128 + kb);
    return sbase + tile * TILE_B + (off ^ ((off >> 3) & 0x70));
}

__global__ __launch_bounds__(256, 1)
void mma_gemm(const float* __restrict__ bias, int pass) {
    extern __shared__ char smem[];
    const uint32_t sb = smem_u32(smem);
    const int tid = threadIdx.x, wid = tid >> 5, lane = tid & 31;
    const int warpM = wid & 3;        // 4 row groups of 32
    const int warpN = wid >> 2;       // 2 col groups of 64
    float* Hout = pass ? g_h2 : g_h;
    const int rowBase = blockIdx.x * 128;

    if (tid < 128) ((float*)(smem + SM_BIAS))[tid] = bias[tid];

    const __nv_bfloat16* tsrc[4] = {
        g_ahi + (size_t)rowBase * 256, g_alo + (size_t)rowBase * 256, g_wth, g_wtl };

    float acc[2][8][4];
#pragma unroll
    for (int mi = 0; mi < 2; mi++)
#pragma unroll
        for (int j = 0; j < 8; j++)
#pragma unroll
            for (int q = 0; q < 4; q++) acc[mi][j][q] = 0.f;

    // per-lane ldmatrix row/kb components
    const int lrr  = (lane & 7) + ((lane >> 3) & 1) * 8;   // row offset within 16
    const int lkb  = (lane >> 4) * 16;                     // byte offset within 32

#pragma unroll 1
    for (int c = 0; c < 4; c++) {
        // stage 4 tiles: [128 rows][64 bf16] each, swizzled
#pragma unroll
        for (int t = 0; t < 4; t++) {
            const __nv_bfloat16* src = tsrc[t] + c * 64;
            char* dst = smem + t * TILE_B;
#pragma unroll
            for (int i = tid; i < 1024; i += 256) {
                int r = i >> 3, q = i & 7;
                uint32_t off = (uint32_t)(r * 128 + q * 16);
                uint32_t sw = off ^ ((off >> 3) & 0x70);
                *(uint4*)(dst + sw) = *(const uint4*)(src + (size_t)r * 256 + q * 8);
            }
        }
        __syncthreads();

#pragma unroll
        for (int ks = 0; ks < 4; ks++) {
            const int kb0 = ks * 32 + lkb;
            uint32_t ah[2][4], al[2][4], wh[4][4], wl[4][4];
#pragma unroll
            for (int mi = 0; mi < 2; mi++) {
                int row = warpM * 32 + mi * 16 + lrr;
                ldsm_x4(ah[mi], sw_addr(sb, 0, row, kb0));
                ldsm_x4(al[mi], sw_addr(sb, 1, row, kb0));
            }
#pragma unroll
            for (int nt = 0; nt < 4; nt++) {
                int nrow = warpN * 64 + nt * 16 + lrr;
                ldsm_x4(wh[nt], sw_addr(sb, 2, nrow, kb0));
                ldsm_x4(wl[nt], sw_addr(sb, 3, nrow, kb0));
            }
#pragma unroll
            for (int mi = 0; mi < 2; mi++)
#pragma unroll
                for (int nt = 0; nt < 4; nt++)
#pragma unroll
                    for (int h = 0; h < 2; h++) {
                        float* cc = acc[mi][nt * 2 + h];
                        mma_bf16(cc, ah[mi], wh[nt][h], wh[nt][2 + h]);
                        mma_bf16(cc, ah[mi], wl[nt][h], wl[nt][2 + h]);
                        mma_bf16(cc, al[mi], wh[nt][h], wh[nt][2 + h]);
                    }
        }
        __syncthreads();
    }

    // epilogue: bias + relu + store (c0,c1 -> row; c2,c3 -> row+8)
    const float* bsm = (const float*)(smem + SM_BIAS);
    const int qr = lane >> 2, qc = (lane & 3) * 2;
#pragma unroll
    for (int mi = 0; mi < 2; mi++) {
        int r0 = rowBase + warpM * 32 + mi * 16 + qr;
#pragma unroll
        for (int j = 0; j < 8; j++) {
            int n = warpN * 64 + (j >> 1) * 16 + (j & 1) * 8 + qc;
            float b0 = bsm[n], b1 = bsm[n + 1];
            float* o0 = Hout + (size_t)r0 * 128 + n;
            float* o1 = Hout + (size_t)(r0 + 8) * 128 + n;
            float2 v0 = make_float2(fmaxf(acc[mi][j][0] + b0, 0.f),
                                    fmaxf(acc[mi][j][1] + b1, 0.f));
            float2 v1 = make_float2(fmaxf(acc[mi][j][2] + b0, 0.f),
                                    fmaxf(acc[mi][j][3] + b1, 0.f));
            *(float2*)o0 = v0;
            *(float2*)o1 = v1;
        }
    }
}

// ---------------- per-graph pooling: score, exact top-K, gate, readout -------
__global__ __launch_bounds__(512)
void pool_kernel(const float* __restrict__ p, int pass) {
    const int b = blockIdx.x;
    float* H   = pass ? g_h2 : g_h;
    float* out = pass ? g_x2 : g_x1;
    const int K = pass ? K2v : K1v;

    __shared__ float sp[128];
    __shared__ float ssc[512];
    __shared__ float sgate[512];
    __shared__ unsigned char skept[512];
    __shared__ float sred[8 * 128];
    __shared__ float s_invn;

    const int tid = threadIdx.x;
    const size_t base = (size_t)b * Nv;

    if (tid < 128) sp[tid] = p[tid];
    __syncthreads();
    if (tid < 32) {
        float v = sp[tid] * sp[tid] + sp[tid + 32] * sp[tid + 32]
                + sp[tid + 64] * sp[tid + 64] + sp[tid + 96] * sp[tid + 96];
        for (int o = 16; o > 0; o >>= 1) v += __shfl_xor_sync(0xffffffffu, v, o);
        if (tid == 0) s_invn = 1.0f / sqrtf(v);
    }
    __syncthreads();

    const int w = tid >> 5, lane = tid & 31;
    for (int it = 0; it < 32; it++) {
        int node = w * 32 + it;
        const float* hr = H + (base + node) * 128;
        float v = hr[lane] * sp[lane] + hr[lane + 32] * sp[lane + 32]
                + hr[lane + 64] * sp[lane + 64] + hr[lane + 96] * sp[lane + 96];
        for (int o = 16; o > 0; o >>= 1) v += __shfl_xor_sync(0xffffffffu, v, o);
        if (lane == 0) {
            float sc = v * s_invn;
            if (pass && !g_m1[base + node]) sc = -INFINITY;
            ssc[node] = sc;
        }
    }
    __syncthreads();

    {
        float my = ssc[tid];
        int cnt = 0;
        for (int j = 0; j < 512; j++) {
            float sj = ssc[j];
            cnt += (sj > my) || (sj == my && j < tid);
        }
        bool kept = cnt < K;
        skept[tid] = kept ? 1 : 0;
        sgate[tid] = kept ? tanhf(my) : 0.f;
        if (!pass) g_m1[base + tid] = kept ? 1 : 0;
    }
    __syncthreads();

    {
        const int f = tid & 127, grp = tid >> 7;
        float fsum = 0.f, fmaxv = -INFINITY;
        for (int n = grp; n < 512; n += 4) {
            size_t gi = (base + n) * 128 + f;
            float v = H[gi] * sgate[n];
            H[gi] = v;
            fsum += v;
            if (skept[n]) fmaxv = fmaxf(fmaxv, v);
        }
        sred[grp * 128 + f]       = fsum;
        sred[512 + grp * 128 + f] = fmaxv;
    }
    __syncthreads();
    if (tid < 128) {
        float s = sred[tid] + sred[128 + tid] + sred[256 + tid] + sred[384 + tid];
        float m = fmaxf(fmaxf(sred[512 + tid], sred[640 + tid]),
                        fmaxf(sred[768 + tid], sred[896 + tid]));
        out[b * 256 + tid]       = m;
        out[b * 256 + 128 + tid] = s / (float)K;
    }
}

// ---------------- MLP head ---------------------------------------------------
__global__ __launch_bounds__(128)
void mlp_kernel(const float* __restrict__ lw1, const float* __restrict__ lb1,
                const float* __restrict__ lw2, const float* __restrict__ lb2,
                const float* __restrict__ lw3, const float* __restrict__ lb3,
                float* __restrict__ outp) {
    const int b = blockIdx.x;
    const int tid = threadIdx.x;  // 128
    __shared__ float sz[256], s1m[128], s2m[64];

    sz[tid]       = g_x1[b * 256 + tid]       + g_x2[b * 256 + tid];
    sz[tid + 128] = g_x1[b * 256 + 128 + tid] + g_x2[b * 256 + 128 + tid];
    __syncthreads();

    float a = lb1[tid];
#pragma unroll 8
    for (int i = 0; i < 256; i++) a += sz[i] * lw1[i * 128 + tid];
    s1m[tid] = fmaxf(a, 0.f);
    __syncthreads();

    if (tid < 64) {
        float a2 = lb2[tid];
#pragma unroll 8
        for (int i = 0; i < 128; i++) a2 += s1m[i] * lw2[i * 64 + tid];
        s2m[tid] = fmaxf(a2, 0.f);
    }
    __syncthreads();

    if (tid < 32) {
        float v = s2m[tid] * lw3[tid] + s2m[tid + 32] * lw3[tid + 32];
        for (int o = 16; o > 0; o >>= 1) v += __shfl_xor_sync(0xffffffffu, v, o);
        if (tid == 0) outp[b] = 1.0f / (1.0f + expf(-(v + lb3[0])));
    }
}

// ---------------- launch -----------------------------------------------------
extern "C" void kernel_launch(void* const* d_in, const int* in_sizes, int n_in,
                              void* d_out, int out_size) {
    const float* x   = (const float*)d_in[0];
    const int*   ei  = (const int*)  d_in[1];
    const float* W1r = (const float*)d_in[2];
    const float* W1n = (const float*)d_in[3];
    const float* b1  = (const float*)d_in[4];
    const float* p1  = (const float*)d_in[5];
    const float* W2r = (const float*)d_in[6];
    const float* W2n = (const float*)d_in[7];
    const float* b2  = (const float*)d_in[8];
    const float* p2  = (const float*)d_in[9];
    const float* lw1 = (const float*)d_in[10];
    const float* lb1 = (const float*)d_in[11];
    const float* lw2 = (const float*)d_in[12];
    const float* lb2 = (const float*)d_in[13];
    const float* lw3 = (const float*)d_in[14];
    const float* lb3 = (const float*)d_in[15];
    float* out = (float*)d_out;

    cudaFuncSetAttribute(mma_gemm, cudaFuncAttributeMaxDynamicSharedMemorySize, SM_TOTAL);

    // CSR build (reused by both convs)
    zero_kernel<<<256, 256>>>();
    count_kernel<<<Ev / 256, 256>>>(ei);
    scan_kernel<<<Bv, 512>>>();
    scatter_kernel<<<Ev / 256, 256>>>(ei);

    // conv1
    prep_w<<<128, 256>>>(W1r, W1n);
    aggregate_kernel<<<MTOT / 8, 256>>>(x, 0);
    convert_x<<<MTOT * 128 / 4 / 256, 256>>>(x, 0);
    mma_gemm<<<MTOT / 128, 256, SM_TOTAL>>>(b1, 0);
    pool_kernel<<<Bv, 512>>>(p1, 0);

    // conv2
    prep_w<<<128, 256>>>(W2r, W2n);
    aggregate_kernel<<<MTOT / 8, 256>>>(nullptr, 1);
    convert_x<<<MTOT * 128 / 4 / 256, 256>>>(nullptr, 1);
    mma_gemm<<<MTOT / 128, 256, SM_TOTAL>>>(b2, 1);
    pool_kernel<<<Bv, 512>>>(p2, 1);

    // head
    mlp_kernel<<<Bv, 128>>>(lw1, lb1, lw2, lb2, lw3, lb3, out);
}